// round 2
// baseline (speedup 1.0000x reference)
#include <cuda_runtime.h>
#include <cstdint>

// Problem constants
#define BATCH 16
#define NPER  1310720          // 256*256*20 elements per batch row
#define N4    (NPER/4)         // 327680 float4 per batch
#define BPB   128              // blocks per batch for the big passes
#define T1    256              // threads per block
#define F4B   (N4/BPB)         // 2560 float4 per block
#define IT1   (F4B/T1)         // 10 iterations per block
#define CAP2  786432           // per-batch capacity of stage-2 candidates
#define NBINS 512              // coarse histogram bins (float bits >> 22)

// ---------------- static device scratch (no allocations allowed) ----------
__device__ float    g_cand [(size_t)BATCH * NPER];   // neg candidate values (0 = non-candidate)
__device__ float    g_cand2[(size_t)BATCH * CAP2];   // filtered candidates >= t0
__device__ unsigned g_hist [BATCH * NBINS];
__device__ unsigned g_cnt2 [BATCH];
__device__ double   g_psum [BATCH];
__device__ double   g_msum;
__device__ double   g_train;
__device__ float    g_t0   [BATCH];
__device__ int      g_k    [BATCH];

// ---------------- K0: zero scratch ----------------------------------------
__global__ void k_zero() {
    int i = blockIdx.x * blockDim.x + threadIdx.x;
    if (i < BATCH * NBINS) g_hist[i] = 0u;
    if (i < BATCH) { g_cnt2[i] = 0u; g_psum[i] = 0.0; }
    if (i == 0)   { g_msum = 0.0; g_train = 0.0; }
}

// ---------------- K1: fused elementwise + candidate write + histogram -----
__global__ __launch_bounds__(T1) void k_main(const float4* __restrict__ y,
                                             const float4* __restrict__ o,
                                             const float4* __restrict__ w) {
    __shared__ unsigned hist[8][NBINS];      // per-warp privatized
    __shared__ float rm[8], rp[8];

    const int tid  = threadIdx.x;
    const int warp = tid >> 5;
    const int lane = tid & 31;

    for (int i = tid; i < 8 * NBINS; i += T1) (&hist[0][0])[i] = 0u;
    __syncthreads();

    const int b     = blockIdx.x / BPB;
    const int chunk = blockIdx.x % BPB;
    const size_t base = (size_t)b * N4 + (size_t)chunk * F4B;

    float4* cand4 = reinterpret_cast<float4*>(g_cand);
    unsigned* myh = hist[warp];

    float msum = 0.f, psum = 0.f;

    for (int it = 0; it < IT1; ++it) {
        const size_t idx = base + (size_t)it * T1 + tid;
        const float4 yv = y[idx];
        const float4 ov = o[idx];
        const float4 wv = w[idx];
        float4 cv;

        // warp-aggregated histogram add: lanes sharing a bin elect one leader
#define PROC(comp)                                                          \
        {                                                                   \
            float d = ov.comp - yv.comp;                                    \
            float m = d * d;                                                \
            msum += m;                                                      \
            psum = fmaf(wv.comp, m, psum);                                  \
            bool p = (ov.comp > 0.0f) && (wv.comp == 0.0f);                 \
            float v = p ? m : 0.0f;                                         \
            cv.comp = v;                                                    \
            unsigned bin = __float_as_uint(v) >> 22;                        \
            unsigned act = __ballot_sync(0xffffffffu, p);                   \
            if (p) {                                                        \
                unsigned peers  = __match_any_sync(act, bin);               \
                int      leader = __ffs(peers) - 1;                         \
                if (lane == leader)                                         \
                    atomicAdd(&myh[bin], (unsigned)__popc(peers));          \
            }                                                               \
        }
        PROC(x) PROC(y) PROC(z) PROC(w)
#undef PROC

        cand4[idx] = cv;
    }

    // block reduction of msum / psum
    for (int off = 16; off; off >>= 1) {
        msum += __shfl_down_sync(0xffffffffu, msum, off);
        psum += __shfl_down_sync(0xffffffffu, psum, off);
    }
    if (lane == 0) { rm[warp] = msum; rp[warp] = psum; }
    __syncthreads();
    if (tid == 0) {
        double mm = 0.0, pp = 0.0;
#pragma unroll
        for (int i = 0; i < 8; i++) { mm += (double)rm[i]; pp += (double)rp[i]; }
        atomicAdd(&g_msum, mm);
        atomicAdd(&g_psum[b], pp);
    }

    // merge per-warp histograms into global per-batch histogram
    for (int bin = tid; bin < NBINS; bin += T1) {
        unsigned s = 0;
#pragma unroll
        for (int wp = 0; wp < 8; wp++) s += hist[wp][bin];
        if (s) atomicAdd(&g_hist[b * NBINS + bin], s);
    }
}

// ---------------- K3: per-batch coarse threshold selection -----------------
__global__ void k_sel(const float* __restrict__ ts) {
    int b = threadIdx.x;
    if (b >= BATCH) return;
    int K = (int)ts[b] * 3;                 // NEG_POS_RATIO
    if (K > NPER) K = NPER;
    if (K < 0)    K = 0;
    g_k[b] = K;

    unsigned acc = 0;
    int bstar = 1;                          // bin 0 = zeros/denormal dust: ignored
    for (int bin = NBINS - 1; bin >= 1; --bin) {
        acc += g_hist[b * NBINS + bin];
        if (acc >= (unsigned)K) { bstar = bin; break; }
    }
    g_t0[b] = __uint_as_float((unsigned)bstar << 22);
}

// ---------------- K4: filter candidates >= t0 into small buffer ------------
__global__ __launch_bounds__(T1) void k_filter() {
    __shared__ float    stage[T1 * 4];
    __shared__ unsigned s_cnt, s_base;

    const int tid   = threadIdx.x;
    const int b     = blockIdx.x / BPB;
    const int chunk = blockIdx.x % BPB;
    const size_t base = (size_t)b * N4 + (size_t)chunk * F4B;

    const float4* cand4 = reinterpret_cast<const float4*>(g_cand);
    const float t0 = g_t0[b];
    float* outp = g_cand2 + (size_t)b * CAP2;

    for (int it = 0; it < IT1; ++it) {
        if (tid == 0) s_cnt = 0u;
        __syncthreads();

        const size_t idx = base + (size_t)it * T1 + tid;
        const float4 v = cand4[idx];
        if (v.x >= t0) stage[atomicAdd(&s_cnt, 1u)] = v.x;
        if (v.y >= t0) stage[atomicAdd(&s_cnt, 1u)] = v.y;
        if (v.z >= t0) stage[atomicAdd(&s_cnt, 1u)] = v.z;
        if (v.w >= t0) stage[atomicAdd(&s_cnt, 1u)] = v.w;
        __syncthreads();

        const unsigned c = s_cnt;
        if (tid == 0 && c) s_base = atomicAdd(&g_cnt2[b], c);
        __syncthreads();
        if (c) {
            const unsigned bb = s_base;
            for (unsigned i = tid; i < c; i += T1) {
                unsigned d = bb + i;
                if (d < CAP2) outp[d] = stage[i];
            }
        }
        __syncthreads();
    }
}

// ---------------- K5: exact top-k sum via 4-round radix select -------------
__global__ __launch_bounds__(T1) void k_topk(const float* __restrict__ ts) {
    const int b   = blockIdx.x;
    const int tid = threadIdx.x;

    __shared__ unsigned cnt[256];
    __shared__ float    sm[256];
    __shared__ unsigned sh_prefix;
    __shared__ int      sh_krem;
    __shared__ float    sh_above;
    __shared__ float    red[8];

    const float* vals = g_cand2 + (size_t)b * CAP2;
    unsigned c = g_cnt2[b];
    if (c > CAP2) c = CAP2;
    const int K = g_k[b];

    float negsum = 0.f;

    if (c <= (unsigned)K) {
        // take everything that survived the filter (true only when the batch
        // has fewer than K positive candidates total; zeros contribute 0)
        float acc = 0.f;
        for (unsigned i = tid; i < c; i += T1) acc += vals[i];
        for (int off = 16; off; off >>= 1) acc += __shfl_down_sync(0xffffffffu, acc, off);
        if ((tid & 31) == 0) red[tid >> 5] = acc;
        __syncthreads();
        if (tid == 0) {
#pragma unroll
            for (int i = 0; i < 8; i++) negsum += red[i];
        }
    } else {
        if (tid == 0) { sh_prefix = 0u; sh_krem = K; sh_above = 0.f; }
        for (int r = 0; r < 4; ++r) {
            cnt[tid] = 0u; sm[tid] = 0.f;       // T1 == 256 bins exactly
            __syncthreads();
            const unsigned pfx = sh_prefix;
            const int shift = 24 - 8 * r;
            for (unsigned i = tid; i < c; i += T1) {
                const float v = vals[i];
                const unsigned u = __float_as_uint(v);
                bool match;
                if (r == 0) match = true;
                else        match = (u >> (32 - 8 * r)) == pfx;
                if (match) {
                    const unsigned bin = (u >> shift) & 255u;
                    atomicAdd(&cnt[bin], 1u);
                    atomicAdd(&sm[bin], v);
                }
            }
            __syncthreads();
            if (tid == 0) {
                int krem = sh_krem;
                float sa = sh_above;
                int chosen = 0;
                for (int bin = 255; bin >= 0; --bin) {
                    if ((unsigned)krem <= cnt[bin]) { chosen = bin; break; }
                    krem -= (int)cnt[bin];
                    sa += sm[bin];
                }
                sh_prefix = (sh_prefix << 8) | (unsigned)chosen;
                sh_krem = krem;
                sh_above = sa;
            }
            __syncthreads();
        }
        if (tid == 0)
            negsum = sh_above + (float)sh_krem * __uint_as_float(sh_prefix);
    }

    if (tid == 0) {
        const float t = ts[b];
        const double per = (t > 0.f)
            ? (g_psum[b] + (double)negsum) / (double)t   // ALPHA = 1
            : 0.0;
        atomicAdd(&g_train, per);
    }
}

// ---------------- K6: final scalar -----------------------------------------
__global__ void k_final(float* __restrict__ outp) {
    const double train = g_train / (double)BATCH;
    const double mmean = g_msum / ((double)BATCH * (double)NPER);
    outp[0] = (float)((train + mmean) * 10.0);
}

// ---------------- launch ----------------------------------------------------
extern "C" void kernel_launch(void* const* d_in, const int* in_sizes, int n_in,
                              void* d_out, int out_size) {
    const float4* y  = (const float4*)d_in[0];
    const float4* o  = (const float4*)d_in[1];
    const float4* w  = (const float4*)d_in[2];
    const float*  ts = (const float*)d_in[3];

    k_zero  <<<(BATCH * NBINS + T1 - 1) / T1, T1>>>();
    k_main  <<<BATCH * BPB, T1>>>(y, o, w);
    k_sel   <<<1, 32>>>(ts);
    k_filter<<<BATCH * BPB, T1>>>();
    k_topk  <<<BATCH, T1>>>(ts);
    k_final <<<1, 1>>>((float*)d_out);
}

// round 5
// speedup vs baseline: 3.7753x; 3.7753x over previous
#include <cuda_runtime.h>
#include <cstdint>

// Problem constants
#define BATCH 16
#define NPER  1310720          // 256*256*20 elements per batch row
#define N4    (NPER/4)         // 327680 float4 per batch
#define BPB   128              // blocks per batch for the big passes
#define T1    256              // threads per block
#define F4B   (N4/BPB)         // 2560 float4 per block
#define IT1   (F4B/T1)         // 10 iterations per block
#define CAP2  NPER             // per-batch capacity: can hold ALL elements
#define NBINS 512              // coarse histogram bins (float bits >> 22)
#define SAMPLE_ITERS 2         // histogram built from iterations 0..1 (1/5 sample)
#define SCALE 5                // 10 / SAMPLE_ITERS

// ---------------- static device scratch (no allocations allowed) ----------
__device__ float    g_cand [(size_t)BATCH * NPER];   // neg candidate values (0 = non-candidate)
__device__ float    g_cand2[(size_t)BATCH * CAP2];   // filtered candidates >= t0
__device__ unsigned g_hist [BATCH * NBINS];          // SAMPLED histogram
__device__ unsigned g_cnt2 [BATCH];
__device__ double   g_psum [BATCH];
__device__ double   g_msum;
__device__ double   g_train;
__device__ float    g_t0   [BATCH];
__device__ int      g_k    [BATCH];
__device__ int      g_redo [BATCH];

// ---------------- K0: zero scratch ----------------------------------------
__global__ void k_zero() {
    int i = blockIdx.x * blockDim.x + threadIdx.x;
    if (i < BATCH * NBINS) g_hist[i] = 0u;
    if (i < BATCH) { g_cnt2[i] = 0u; g_psum[i] = 0.0; g_redo[i] = 0; }
    if (i == 0)   { g_msum = 0.0; g_train = 0.0; }
}

// ---------------- K1: fused elementwise + sampled histogram ----------------
__global__ __launch_bounds__(T1) void k_main(const float4* __restrict__ y,
                                             const float4* __restrict__ o,
                                             const float4* __restrict__ w) {
    __shared__ unsigned hist[8][NBINS];      // per-warp privatized
    __shared__ float rm[8], rp[8];

    const int tid  = threadIdx.x;
    const int warp = tid >> 5;
    const int lane = tid & 31;

    for (int i = tid; i < 8 * NBINS; i += T1) (&hist[0][0])[i] = 0u;
    __syncthreads();

    const int b     = blockIdx.x / BPB;
    const int chunk = blockIdx.x % BPB;
    const size_t base = (size_t)b * N4 + (size_t)chunk * F4B;

    float4* cand4 = reinterpret_cast<float4*>(g_cand);
    unsigned* myh = hist[warp];

    float msum = 0.f, psum = 0.f;

#pragma unroll
    for (int it = 0; it < IT1; ++it) {
        const size_t idx = base + (size_t)it * T1 + tid;
        const float4 yv = y[idx];
        const float4 ov = o[idx];
        const float4 wv = w[idx];
        float4 cv;

#define PROC(comp)                                                          \
        {                                                                   \
            float d = ov.comp - yv.comp;                                    \
            float m = d * d;                                                \
            msum += m;                                                      \
            psum = fmaf(wv.comp, m, psum);                                  \
            bool p = (ov.comp > 0.0f) && (wv.comp == 0.0f);                 \
            float v = p ? m : 0.0f;                                         \
            cv.comp = v;                                                    \
            if (it < SAMPLE_ITERS) {  /* compile-time pruned per iter */    \
                if (p) atomicAdd(&myh[__float_as_uint(v) >> 22], 1u);       \
            }                                                               \
        }
        PROC(x) PROC(y) PROC(z) PROC(w)
#undef PROC

        cand4[idx] = cv;
    }

    // block reduction of msum / psum
    for (int off = 16; off; off >>= 1) {
        msum += __shfl_down_sync(0xffffffffu, msum, off);
        psum += __shfl_down_sync(0xffffffffu, psum, off);
    }
    if (lane == 0) { rm[warp] = msum; rp[warp] = psum; }
    __syncthreads();
    if (tid == 0) {
        double mm = 0.0, pp = 0.0;
#pragma unroll
        for (int i = 0; i < 8; i++) { mm += (double)rm[i]; pp += (double)rp[i]; }
        atomicAdd(&g_msum, mm);
        atomicAdd(&g_psum[b], pp);
    }

    // merge per-warp sampled histograms into global per-batch histogram
    for (int bin = tid; bin < NBINS; bin += T1) {
        unsigned s = 0;
#pragma unroll
        for (int wp = 0; wp < 8; wp++) s += hist[wp][bin];
        if (s) atomicAdd(&g_hist[b * NBINS + bin], s);
    }
}

// ---------------- K3: per-batch conservative threshold from sampled hist ---
__global__ void k_sel(const float* __restrict__ ts) {
    int b = threadIdx.x;
    if (b >= BATCH) return;
    long long K = (long long)((int)ts[b]) * 3;     // NEG_POS_RATIO
    if (K > NPER) K = NPER;
    if (K < 0)    K = 0;
    g_k[b] = (int)K;

    if (K == 0) { g_t0[b] = 3.4e38f; return; }     // nothing needed

    const long long target = 2 * K + 64;           // safety margin (x2 + slack)
    unsigned long long acc = 0;
    int bstar = 0;
    for (int bin = NBINS - 1; bin >= 1; --bin) {
        acc += g_hist[b * NBINS + bin];
        if ((long long)(acc * SCALE) >= target) { bstar = bin; break; }
    }
    // bstar==0: not enough candidates even at the bottom -> take all positives
    g_t0[b] = (bstar == 0) ? 1.4e-45f : __uint_as_float((unsigned)bstar << 22);
}

// ---------------- K4: warp-compaction filter (v >= t0) ---------------------
__device__ __forceinline__ void filter_body(int b, int chunk) {
    const int tid  = threadIdx.x;
    const int lane = tid & 31;
    const size_t base = (size_t)b * N4 + (size_t)chunk * F4B;

    const float4* cand4 = reinterpret_cast<const float4*>(g_cand);
    const float t0 = g_t0[b];
    float* outp = g_cand2 + (size_t)b * CAP2;
    const unsigned lt = (1u << lane) - 1u;

#pragma unroll
    for (int it = 0; it < IT1; ++it) {     // trip count warp-uniform: collectives safe
        const size_t idx = base + (size_t)it * T1 + tid;
        const float4 v = cand4[idx];
        const bool p0 = v.x >= t0, p1 = v.y >= t0, p2 = v.z >= t0, p3 = v.w >= t0;
        const unsigned m0 = __ballot_sync(0xffffffffu, p0);
        const unsigned m1 = __ballot_sync(0xffffffffu, p1);
        const unsigned m2 = __ballot_sync(0xffffffffu, p2);
        const unsigned m3 = __ballot_sync(0xffffffffu, p3);
        const unsigned c0 = __popc(m0), c1 = __popc(m1), c2 = __popc(m2), c3 = __popc(m3);
        const unsigned tot = c0 + c1 + c2 + c3;
        if (tot == 0) continue;            // tot is warp-uniform
        unsigned basew = 0;
        if (lane == 0) basew = atomicAdd(&g_cnt2[b], tot);
        basew = __shfl_sync(0xffffffffu, basew, 0);
        if (p0) outp[basew + __popc(m0 & lt)] = v.x;
        if (p1) outp[basew + c0 + __popc(m1 & lt)] = v.y;
        if (p2) outp[basew + c0 + c1 + __popc(m2 & lt)] = v.z;
        if (p3) outp[basew + c0 + c1 + c2 + __popc(m3 & lt)] = v.w;
    }
}

__global__ __launch_bounds__(T1) void k_filter() {
    filter_body(blockIdx.x / BPB, blockIdx.x % BPB);
}

// ---------------- K4b: verify survivor count; arm fallback -----------------
__global__ void k_check() {
    int b = threadIdx.x;
    if (b >= BATCH) return;
    const unsigned c = g_cnt2[b];
    const int K = g_k[b];
    if (c < (unsigned)K) {               // sampled threshold missed -> take all positives
        g_redo[b] = 1;
        g_cnt2[b] = 0u;
        g_t0[b]   = 1.4e-45f;            // v >= min denorm  <=>  v > 0
    }
}

// ---------------- K4c: fallback refilter (no-op unless armed) --------------
__global__ __launch_bounds__(T1) void k_filter2() {
    const int b = blockIdx.x / BPB;
    if (!g_redo[b]) return;
    filter_body(b, blockIdx.x % BPB);
}

// ---------------- K5: exact top-k sum: counts-only radix + sum pass --------
__global__ __launch_bounds__(T1) void k_topk(const float* __restrict__ ts) {
    const int b    = blockIdx.x;
    const int tid  = threadIdx.x;
    const int lane = tid & 31;

    __shared__ unsigned cnt[256];
    __shared__ unsigned sh_prefix;
    __shared__ int      sh_krem;
    __shared__ double   red[8];

    const float* vals = g_cand2 + (size_t)b * CAP2;
    const unsigned c  = g_cnt2[b];
    const int K = g_k[b];

    double negsum = 0.0;

    if (c <= (unsigned)K) {
        // survivors are ALL positive candidates (guaranteed by k_check) -> sum all
        float acc = 0.f;
        for (unsigned i = tid; i < c; i += T1) acc += vals[i];
        for (int off = 16; off; off >>= 1) acc += __shfl_down_sync(0xffffffffu, acc, off);
        if (lane == 0) red[tid >> 5] = (double)acc;
        __syncthreads();
        if (tid == 0) {
#pragma unroll
            for (int i = 0; i < 8; i++) negsum += red[i];
        }
    } else {
        if (tid == 0) { sh_prefix = 0u; sh_krem = K; }
        // padded loop bound so ALL lanes reach every warp collective
        const unsigned cpad = ((c + T1 - 1) / T1) * T1;
        for (int r = 0; r < 4; ++r) {
            cnt[tid] = 0u;
            __syncthreads();
            const unsigned pfx = sh_prefix;
            const int shift = 24 - 8 * r;
            for (unsigned i = tid; i < cpad; i += T1) {
                const bool valid = (i < c);
                const unsigned u = valid ? __float_as_uint(vals[i]) : 0u;
                const bool match = valid && ((r == 0) || ((u >> (32 - 8 * r)) == pfx));
                const unsigned bin = (u >> shift) & 255u;
                const unsigned act = __ballot_sync(0xffffffffu, match);
                if (match) {
                    const unsigned peers = __match_any_sync(act, bin);
                    if (lane == (__ffs(peers) - 1))
                        atomicAdd(&cnt[bin], (unsigned)__popc(peers));
                }
            }
            __syncthreads();
            if (tid == 0) {
                int krem = sh_krem;
                int chosen = 0;
                for (int bin = 255; bin >= 0; --bin) {
                    if ((unsigned)krem <= cnt[bin]) { chosen = bin; break; }
                    krem -= (int)cnt[bin];
                }
                sh_prefix = (sh_prefix << 8) | (unsigned)chosen;
                sh_krem = krem;
            }
            __syncthreads();
        }
        // sum pass: strictly-above sum (bit compare valid for positive floats)
        const unsigned thr = sh_prefix;
        float acc = 0.f;
        for (unsigned i = tid; i < c; i += T1) {
            const float v = vals[i];
            if (__float_as_uint(v) > thr) acc += v;
        }
        for (int off = 16; off; off >>= 1) acc += __shfl_down_sync(0xffffffffu, acc, off);
        if (lane == 0) red[tid >> 5] = (double)acc;
        __syncthreads();
        if (tid == 0) {
#pragma unroll
            for (int i = 0; i < 8; i++) negsum += red[i];
            negsum += (double)sh_krem * (double)__uint_as_float(thr);  // ties at threshold
        }
    }

    if (tid == 0) {
        const float t = ts[b];
        const double per = (t > 0.f)
            ? (g_psum[b] + negsum) / (double)t     // ALPHA = 1
            : 0.0;
        atomicAdd(&g_train, per);
    }
}

// ---------------- K6: final scalar -----------------------------------------
__global__ void k_final(float* __restrict__ outp) {
    const double train = g_train / (double)BATCH;
    const double mmean = g_msum / ((double)BATCH * (double)NPER);
    outp[0] = (float)((train + mmean) * 10.0);
}

// ---------------- launch ----------------------------------------------------
extern "C" void kernel_launch(void* const* d_in, const int* in_sizes, int n_in,
                              void* d_out, int out_size) {
    const float4* y  = (const float4*)d_in[0];
    const float4* o  = (const float4*)d_in[1];
    const float4* w  = (const float4*)d_in[2];
    const float*  ts = (const float*)d_in[3];

    k_zero   <<<(BATCH * NBINS + T1 - 1) / T1, T1>>>();
    k_main   <<<BATCH * BPB, T1>>>(y, o, w);
    k_sel    <<<1, 32>>>(ts);
    k_filter <<<BATCH * BPB, T1>>>();
    k_check  <<<1, 32>>>();
    k_filter2<<<BATCH * BPB, T1>>>();
    k_topk   <<<BATCH, T1>>>(ts);
    k_final  <<<1, 1>>>((float*)d_out);
}